// round 15
// baseline (speedup 1.0000x reference)
#include <cuda_runtime.h>
#include <cstdint>
#include <math.h>

#define BB 32
#define CC 256
#define CR 64
#define HW 16384            // 128*128
#define NROWS (BB * CC)     // 8192 blocks, one per (b,c) row

// allocation-free scratch
__device__ float g_f0[BB * CC];
__device__ int   g_counter;   // finish tickets (zero-init; reset each call)
__device__ int   g_done;      // epilogue blocks completed

__device__ __forceinline__ void prefetchL2(const void* p) {
    asm volatile("prefetch.global.L2 [%0];" :: "l"(p));
}

// ---------------------------------------------------------------------------
// Single kernel. Every block: row mean of one (b,c) row. Block 0 additionally
// prefetches all weights into L2 at start. The last 32 blocks to finish
// (by ticket) each run the full SE-MLP for one batch element, reading weights
// from (warm) L2 with coalesced, ILP-8 access.
// ---------------------------------------------------------------------------
__global__ __launch_bounds__(256) void fused_se_kernel(const float* __restrict__ x,
                                                       const float* __restrict__ W1,
                                                       const float* __restrict__ W2,
                                                       const float* __restrict__ W3,
                                                       const float* __restrict__ b3,
                                                       float* __restrict__ out) {
    const int t = threadIdx.x;

    // ---- L2 weight prefetch (block 0 only; 1056 lines total) --------------
    if (blockIdx.x == 0) {
        const char* w1 = (const char*)W1;   // 64 KB
        const char* w2 = (const char*)W2;   // 64 KB
#pragma unroll
        for (int k = 0; k < 2; k++) {
            prefetchL2(w1 + (k * 256 + t) * 128);
            prefetchL2(w2 + (k * 256 + t) * 128);
        }
        if (t < 16) prefetchL2((const char*)W3 + t * 128);
    }

    // ======================= row mean (all blocks) =========================
    const int row = blockIdx.x;                  // b*C + c
    {
        const float4* __restrict__ p =
            reinterpret_cast<const float4*>(x) + (size_t)row * (HW / 4);

        float s = 0.0f;
#pragma unroll
        for (int k = 0; k < 16; k++) {
            float4 v = __ldcs(p + k * 256 + t);
            s += (v.x + v.y) + (v.z + v.w);
        }
#pragma unroll
        for (int o = 16; o > 0; o >>= 1)
            s += __shfl_xor_sync(0xffffffffu, s, o);

        __shared__ float part[8];
        if ((t & 31) == 0) part[t >> 5] = s;
        __syncthreads();

        if (t < 8) {
            float v = part[t];
#pragma unroll
            for (int o = 4; o > 0; o >>= 1)
                v += __shfl_xor_sync(0x000000ffu, v, o);
            if (t == 0) g_f0[row] = v * (1.0f / HW);
        }
    }

    // ---- take a finish ticket --------------------------------------------
    __shared__ int s_ticket;
    if (t == 0) {
        __threadfence();
        s_ticket = atomicAdd(&g_counter, 1);
    }
    __syncthreads();
    const int ticket = s_ticket;
    if (ticket < NROWS - BB) return;            // not one of the last 32

    // ================== epilogue: SE-MLP for batch b =======================
    const int b    = ticket - (NROWS - BB);
    const int warp = t >> 5;
    const int lane = t & 31;

    if (t == 0) {
        while (atomicAdd(&g_counter, 0) < NROWS) __nanosleep(64);
    }
    __syncthreads();
    __threadfence();

    __shared__ float f0s[CC];
    __shared__ float hs[CR];
    __shared__ float ps[CC];

    if (t < CC) f0s[t] = g_f0[b * CC + t];
    __syncthreads();

    // ---- stage 1: h[j] = relu(f0 . W1[j,:]), 8 outputs/warp, ILP8 ---------
    {
        float acc[8];
#pragma unroll
        for (int u = 0; u < 8; u++) acc[u] = 0.0f;
#pragma unroll
        for (int k = 0; k < 8; k++) {
            const int c = k * 32 + lane;
            const float f = f0s[c];
#pragma unroll
            for (int u = 0; u < 8; u++)
                acc[u] = fmaf(f, __ldg(W1 + (warp * 8 + u) * CC + c), acc[u]);
        }
#pragma unroll
        for (int o = 16; o > 0; o >>= 1)
#pragma unroll
            for (int u = 0; u < 8; u++)
                acc[u] += __shfl_xor_sync(0xffffffffu, acc[u], o);
        if (lane == 0) {
#pragma unroll
            for (int u = 0; u < 8; u++)
                hs[warp * 8 + u] = fmaxf(acc[u], 0.0f);
        }
    }
    __syncthreads();

    // ---- stage 2: p[c] = sigmoid(h . W2[c,:]) * f0[c], 32 outputs/warp ----
    {
        const float hv0 = hs[lane];
        const float hv1 = hs[lane + 32];
#pragma unroll
        for (int g = 0; g < 4; g++) {
            float acc[8];
#pragma unroll
            for (int u = 0; u < 8; u++) {
                const int c = warp * 32 + g * 8 + u;
                const float* __restrict__ w = W2 + c * CR;
                acc[u] = fmaf(hv0, __ldg(w + lane), hv1 * __ldg(w + lane + 32));
            }
#pragma unroll
            for (int o = 16; o > 0; o >>= 1)
#pragma unroll
                for (int u = 0; u < 8; u++)
                    acc[u] += __shfl_xor_sync(0xffffffffu, acc[u], o);
            if (lane == 0) {
#pragma unroll
                for (int u = 0; u < 8; u++) {
                    const int c = warp * 32 + g * 8 + u;
                    const float gsig = 1.0f / (1.0f + __expf(-acc[u]));
                    ps[c] = gsig * f0s[c];
                }
            }
        }
    }
    __syncthreads();

    // ---- stage 3: out[b,o] = p . W3[o,:] + b3[o] --------------------------
    if (warp < 2) {
        const int o = warp;
        const float* __restrict__ w = W3 + o * CC;
        float acc = 0.0f;
#pragma unroll
        for (int k = 0; k < 8; k++) {
            const int c = k * 32 + lane;
            acc = fmaf(ps[c], __ldg(w + c), acc);
        }
#pragma unroll
        for (int s = 16; s > 0; s >>= 1)
            acc += __shfl_xor_sync(0xffffffffu, acc, s);
        if (lane == 0) out[b * 2 + o] = acc + b3[o];
    }
    __syncthreads();

    // ---- deterministic reset for graph replay -----------------------------
    if (t == 0) {
        __threadfence();
        const int d = atomicAdd(&g_done, 1);
        if (d == BB - 1) {          // last epilogue block resets both counters
            g_counter = 0;
            g_done    = 0;
            __threadfence();
        }
    }
}

// ---------------------------------------------------------------------------
extern "C" void kernel_launch(void* const* d_in, const int* in_sizes, int n_in,
                              void* d_out, int out_size) {
    const float* x  = (const float*)d_in[0];  // (32,256,128,128)
    const float* W1 = (const float*)d_in[1];  // (64,256)
    const float* W2 = (const float*)d_in[2];  // (256,64)
    const float* W3 = (const float*)d_in[3];  // (2,256)
    const float* b3 = (const float*)d_in[4];  // (2,)
    float* out = (float*)d_out;               // (32,2)

    fused_se_kernel<<<NROWS, 256>>>(x, W1, W2, W3, b3, out);
}

// round 16
// speedup vs baseline: 1.1648x; 1.1648x over previous
#include <cuda_runtime.h>
#include <cstdint>
#include <math.h>

#define BB 32
#define CC 256
#define CR 64
#define HW 16384   // 128*128

// allocation-free scratch: pooled means
__device__ float g_f0[BB * CC];

// ---------------------------------------------------------------------------
// Kernel 1: f0[b,c] = mean over H*W of x[b,c,:,:]  (pure DRAM stream)
// ---------------------------------------------------------------------------
__global__ __launch_bounds__(256) void row_mean_kernel(const float* __restrict__ x) {
    const int row = blockIdx.x;                  // b*C + c
    const float4* __restrict__ p =
        reinterpret_cast<const float4*>(x) + (size_t)row * (HW / 4);
    const int t = threadIdx.x;

    float s = 0.0f;
#pragma unroll
    for (int k = 0; k < 16; k++) {
        float4 v = __ldcs(p + k * 256 + t);
        s += (v.x + v.y) + (v.z + v.w);
    }
#pragma unroll
    for (int o = 16; o > 0; o >>= 1)
        s += __shfl_xor_sync(0xffffffffu, s, o);

    __shared__ float part[8];
    if ((t & 31) == 0) part[t >> 5] = s;
    __syncthreads();

    if (t < 8) {
        float v = part[t];
#pragma unroll
        for (int o = 4; o > 0; o >>= 1)
            v += __shfl_xor_sync(0x000000ffu, v, o);
        if (t == 0) {
            g_f0[row] = v * (1.0f / HW);
            __threadfence();
        }
    }
    __syncthreads();
    if (t == 0)
        asm volatile("griddepcontrol.launch_dependents;");
}

// ---------------------------------------------------------------------------
// Kernel 2: fused SE-MLP, one block per batch element (PDL dependent).
// NO big smem (2.3 KB static only) -> no carveout reconfig, no 1-block/SM cap.
// Weights read directly from GMEM, coalesced, ILP-8 (latency-tolerant).
// ---------------------------------------------------------------------------
__global__ __launch_bounds__(256) void fused_mlp_kernel(const float* __restrict__ W1,
                                                        const float* __restrict__ W2,
                                                        const float* __restrict__ W3,
                                                        const float* __restrict__ b3,
                                                        float* __restrict__ out) {
    __shared__ float f0s[CC];
    __shared__ float hs[CR];
    __shared__ float ps[CC];

    const int b    = blockIdx.x;
    const int t    = threadIdx.x;
    const int warp = t >> 5;
    const int lane = t & 31;

    // wait for primary grid's g_f0 writes to be complete & visible
    asm volatile("griddepcontrol.wait;" ::: "memory");

    if (t < CC) f0s[t] = g_f0[b * CC + t];
    __syncthreads();

    // ---- stage 1: h[j] = relu(f0 . W1[j,:]), 8 outputs/warp, ILP8 ---------
    {
        float acc[8];
#pragma unroll
        for (int u = 0; u < 8; u++) acc[u] = 0.0f;
#pragma unroll
        for (int k = 0; k < 8; k++) {
            const int c = k * 32 + lane;
            const float f = f0s[c];
#pragma unroll
            for (int u = 0; u < 8; u++)
                acc[u] = fmaf(f, __ldg(W1 + (warp * 8 + u) * CC + c), acc[u]);
        }
#pragma unroll
        for (int o = 16; o > 0; o >>= 1)
#pragma unroll
            for (int u = 0; u < 8; u++)
                acc[u] += __shfl_xor_sync(0xffffffffu, acc[u], o);
        if (lane == 0) {
#pragma unroll
            for (int u = 0; u < 8; u++)
                hs[warp * 8 + u] = fmaxf(acc[u], 0.0f);
        }
    }
    __syncthreads();

    // ---- stage 2: p[c] = sigmoid(h . W2[c,:]) * f0[c], 32 outputs/warp ----
    {
        const float hv0 = hs[lane];
        const float hv1 = hs[lane + 32];
#pragma unroll
        for (int g = 0; g < 4; g++) {
            float acc[8];
#pragma unroll
            for (int u = 0; u < 8; u++) {
                const int c = warp * 32 + g * 8 + u;
                const float* __restrict__ w = W2 + c * CR;
                acc[u] = fmaf(hv0, __ldg(w + lane), hv1 * __ldg(w + lane + 32));
            }
#pragma unroll
            for (int o = 16; o > 0; o >>= 1)
#pragma unroll
                for (int u = 0; u < 8; u++)
                    acc[u] += __shfl_xor_sync(0xffffffffu, acc[u], o);
            if (lane == 0) {
#pragma unroll
                for (int u = 0; u < 8; u++) {
                    const int c = warp * 32 + g * 8 + u;
                    const float gsig = 1.0f / (1.0f + __expf(-acc[u]));
                    ps[c] = gsig * f0s[c];
                }
            }
        }
    }
    __syncthreads();

    // ---- stage 3: out[b,o] = p . W3[o,:] + b3[o] --------------------------
    if (warp < 2) {
        const int o = warp;
        const float* __restrict__ w = W3 + o * CC;
        float acc = 0.0f;
#pragma unroll
        for (int k = 0; k < 8; k++) {
            const int c = k * 32 + lane;
            acc = fmaf(ps[c], __ldg(w + c), acc);
        }
#pragma unroll
        for (int s = 16; s > 0; s >>= 1)
            acc += __shfl_xor_sync(0xffffffffu, acc, s);
        if (lane == 0) out[b * 2 + o] = acc + b3[o];
    }
}

// ---------------------------------------------------------------------------
extern "C" void kernel_launch(void* const* d_in, const int* in_sizes, int n_in,
                              void* d_out, int out_size) {
    const float* x  = (const float*)d_in[0];  // (32,256,128,128)
    const float* W1 = (const float*)d_in[1];  // (64,256)
    const float* W2 = (const float*)d_in[2];  // (256,64)
    const float* W3 = (const float*)d_in[3];  // (2,256)
    const float* b3 = (const float*)d_in[4];  // (2,)
    float* out = (float*)d_out;               // (32,2)

    row_mean_kernel<<<BB * CC, 256>>>(x);

    cudaLaunchConfig_t cfg = {};
    cfg.gridDim          = dim3(BB);
    cfg.blockDim         = dim3(256);
    cfg.dynamicSmemBytes = 0;
    cfg.stream           = 0;
    cudaLaunchAttribute attrs[1];
    attrs[0].id = cudaLaunchAttributeProgrammaticStreamSerialization;
    attrs[0].val.programmaticStreamSerializationAllowed = 1;
    cfg.attrs    = attrs;
    cfg.numAttrs = 1;
    cudaLaunchKernelEx(&cfg, fused_mlp_kernel, W1, W2, W3, b3, out);
}

// round 17
// speedup vs baseline: 1.2263x; 1.0528x over previous
#include <cuda_runtime.h>
#include <cstdint>
#include <math.h>

#define BB 32
#define CC 256
#define CR 64
#define HW 16384            // 128*128
#define NROWS (BB * CC)     // 8192 rows
#define GRID1 1184          // 148 SMs x 8 resident CTAs: single-wave persistent

// allocation-free scratch: pooled means
__device__ float g_f0[BB * CC];

// dynamic smem layout (floats):
//   W1s [CR*CC] | W2s [CC*CR] | W3s [2*CC] | f0s [CC] | hs [CR] | ps [CC]
#define SMEM_FLOATS (CR * CC + CC * CR + 2 * CC + CC + CR + CC)
#define SMEM_BYTES  (SMEM_FLOATS * 4)

// 16-byte async copy GMEM -> SMEM, no register involvement (LDGSTS)
__device__ __forceinline__ void cp16(unsigned int dst_smem, const void* src) {
    asm volatile("cp.async.cg.shared.global [%0], [%1], 16;"
                 :: "r"(dst_smem), "l"(src) : "memory");
}

// ---------------------------------------------------------------------------
// Kernel 1: persistent row-mean. 1184 blocks, each reduces ~7 rows.
// Single wave -> no wave-transition overhead, balanced finish for PDL.
// ---------------------------------------------------------------------------
__global__ __launch_bounds__(256) void row_mean_kernel(const float* __restrict__ x) {
    const int t = threadIdx.x;
    __shared__ float part[8];

    for (int row = blockIdx.x; row < NROWS; row += GRID1) {
        const float4* __restrict__ p =
            reinterpret_cast<const float4*>(x) + (size_t)row * (HW / 4);

        float s = 0.0f;
#pragma unroll
        for (int k = 0; k < 16; k++) {
            float4 v = __ldcs(p + k * 256 + t);
            s += (v.x + v.y) + (v.z + v.w);
        }
#pragma unroll
        for (int o = 16; o > 0; o >>= 1)
            s += __shfl_xor_sync(0xffffffffu, s, o);

        if ((t & 31) == 0) part[t >> 5] = s;
        __syncthreads();

        if (t < 8) {
            float v = part[t];
#pragma unroll
            for (int o = 4; o > 0; o >>= 1)
                v += __shfl_xor_sync(0x000000ffu, v, o);
            if (t == 0) g_f0[row] = v * (1.0f / HW);
        }
        __syncthreads();
    }

    __threadfence();
    if (t == 0)
        asm volatile("griddepcontrol.launch_dependents;");
}

// ---------------------------------------------------------------------------
// Kernel 2: fused SE-MLP, one block per batch element (PDL dependent).
// cp.async burst of all weights into smem (no register cap), then all three
// stages from smem. (R14 configuration — best measured MLP variant.)
// ---------------------------------------------------------------------------
__global__ __launch_bounds__(256) void fused_mlp_kernel(const float* __restrict__ W1,
                                                        const float* __restrict__ W2,
                                                        const float* __restrict__ W3,
                                                        const float* __restrict__ b3,
                                                        float* __restrict__ out) {
    extern __shared__ float sw[];
    float* W1s = sw;                       // CR*CC = 16384
    float* W2s = W1s + CR * CC;            // CC*CR = 16384
    float* W3s = W2s + CC * CR;            // 2*CC  = 512
    float* f0s = W3s + 2 * CC;             // 256
    float* hs  = f0s + CC;                 // 64
    float* ps  = hs + CR;                  // 256

    const int b    = blockIdx.x;
    const int t    = threadIdx.x;
    const int warp = t >> 5;
    const int lane = t & 31;

    // ---- step 0: async weight burst (all LDGSTS independent, in-flight) ---
    {
        const unsigned int w1d = (unsigned int)__cvta_generic_to_shared(W1s);
        const unsigned int w2d = (unsigned int)__cvta_generic_to_shared(W2s);
        const unsigned int w3d = (unsigned int)__cvta_generic_to_shared(W3s);
        const float4* __restrict__ s1 = reinterpret_cast<const float4*>(W1);
        const float4* __restrict__ s2 = reinterpret_cast<const float4*>(W2);
        const float4* __restrict__ s3 = reinterpret_cast<const float4*>(W3);
#pragma unroll
        for (int k = 0; k < 16; k++)
            cp16(w1d + (k * 256 + t) * 16, s1 + k * 256 + t);
#pragma unroll
        for (int k = 0; k < 16; k++)
            cp16(w2d + (k * 256 + t) * 16, s2 + k * 256 + t);
        if (t < 128)
            cp16(w3d + t * 16, s3 + t);
        asm volatile("cp.async.commit_group;" ::: "memory");
    }

    // wait for primary grid's g_f0 writes to be complete & visible
    asm volatile("griddepcontrol.wait;" ::: "memory");

    if (t < CC) f0s[t] = g_f0[b * CC + t];

    asm volatile("cp.async.wait_group 0;" ::: "memory");
    __syncthreads();

    // ---- stage 1: h[j] = relu(f0 . W1[j,:]), 8 outputs/warp, ILP8 ---------
    {
        float acc[8];
#pragma unroll
        for (int u = 0; u < 8; u++) acc[u] = 0.0f;
#pragma unroll
        for (int k = 0; k < 8; k++) {
            const int c = k * 32 + lane;
            const float f = f0s[c];
#pragma unroll
            for (int u = 0; u < 8; u++)
                acc[u] = fmaf(f, W1s[(warp * 8 + u) * CC + c], acc[u]);
        }
#pragma unroll
        for (int o = 16; o > 0; o >>= 1)
#pragma unroll
            for (int u = 0; u < 8; u++)
                acc[u] += __shfl_xor_sync(0xffffffffu, acc[u], o);
        if (lane == 0) {
#pragma unroll
            for (int u = 0; u < 8; u++)
                hs[warp * 8 + u] = fmaxf(acc[u], 0.0f);
        }
    }
    __syncthreads();

    // ---- stage 2: p[c] = sigmoid(h . W2[c,:]) * f0[c], 32 outputs/warp ----
    {
        const float hv0 = hs[lane];
        const float hv1 = hs[lane + 32];
#pragma unroll
        for (int g = 0; g < 4; g++) {
            float acc[8];
#pragma unroll
            for (int u = 0; u < 8; u++) {
                const int c = warp * 32 + g * 8 + u;
                const float* __restrict__ w = W2s + c * CR;
                acc[u] = fmaf(hv0, w[lane], hv1 * w[lane + 32]);
            }
#pragma unroll
            for (int o = 16; o > 0; o >>= 1)
#pragma unroll
                for (int u = 0; u < 8; u++)
                    acc[u] += __shfl_xor_sync(0xffffffffu, acc[u], o);
            if (lane == 0) {
#pragma unroll
                for (int u = 0; u < 8; u++) {
                    const int c = warp * 32 + g * 8 + u;
                    const float gsig = 1.0f / (1.0f + __expf(-acc[u]));
                    ps[c] = gsig * f0s[c];
                }
            }
        }
    }
    __syncthreads();

    // ---- stage 3: out[b,o] = p . W3[o,:] + b3[o] --------------------------
    if (warp < 2) {
        const int o = warp;
        const float* __restrict__ w = W3s + o * CC;
        float acc = 0.0f;
#pragma unroll
        for (int k = 0; k < 8; k++) {
            const int c = k * 32 + lane;
            acc = fmaf(ps[c], w[c], acc);
        }
#pragma unroll
        for (int s = 16; s > 0; s >>= 1)
            acc += __shfl_xor_sync(0xffffffffu, acc, s);
        if (lane == 0) out[b * 2 + o] = acc + b3[o];
    }
}

// ---------------------------------------------------------------------------
extern "C" void kernel_launch(void* const* d_in, const int* in_sizes, int n_in,
                              void* d_out, int out_size) {
    const float* x  = (const float*)d_in[0];  // (32,256,128,128)
    const float* W1 = (const float*)d_in[1];  // (64,256)
    const float* W2 = (const float*)d_in[2];  // (256,64)
    const float* W3 = (const float*)d_in[3];  // (2,256)
    const float* b3 = (const float*)d_in[4];  // (2,)
    float* out = (float*)d_out;               // (32,2)

    cudaFuncSetAttribute(fused_mlp_kernel,
                         cudaFuncAttributeMaxDynamicSharedMemorySize, SMEM_BYTES);

    row_mean_kernel<<<GRID1, 256>>>(x);

    cudaLaunchConfig_t cfg = {};
    cfg.gridDim          = dim3(BB);
    cfg.blockDim         = dim3(256);
    cfg.dynamicSmemBytes = SMEM_BYTES;
    cfg.stream           = 0;
    cudaLaunchAttribute attrs[1];
    attrs[0].id = cudaLaunchAttributeProgrammaticStreamSerialization;
    attrs[0].val.programmaticStreamSerializationAllowed = 1;
    cfg.attrs    = attrs;
    cfg.numAttrs = 1;
    cudaLaunchKernelEx(&cfg, fused_mlp_kernel, W1, W2, W3, b3, out);
}